// round 1
// baseline (speedup 1.0000x reference)
#include <cuda_runtime.h>
#include <cuda_bf16.h>
#include <cstdint>

// Problem constants (shapes are fixed by the dataset).
#define N_NODES_MAX 50000
#define CH 128            // IN_CH == OUT_CH == 128

// -------- device scratch (no allocations allowed) --------
__device__ float g_h[(size_t)N_NODES_MAX * CH];   // x @ W
__device__ int   g_deg[N_NODES_MAX];
__device__ float g_dinv[N_NODES_MAX];

// -------- kernel 1: deg init (self-loop counts as 1) --------
__global__ void k_init_deg(int n) {
    int i = blockIdx.x * blockDim.x + threadIdx.x;
    if (i < n) g_deg[i] = 1;
}

// -------- kernel 2: histogram over dst --------
__global__ void k_count(const int* __restrict__ dst, int E) {
    int e = blockIdx.x * blockDim.x + threadIdx.x;
    if (e < E) atomicAdd(&g_deg[dst[e]], 1);
}

// -------- kernel 3: dinv = rsqrt(deg) --------
__global__ void k_dinv(int n) {
    int i = blockIdx.x * blockDim.x + threadIdx.x;
    if (i < n) g_dinv[i] = rsqrtf((float)g_deg[i]);
}

// -------- kernel 4: GEMM h = x @ W, fp32, shared-tiled --------
// Block computes a 128x128 tile; 256 threads, each 8x8 micro-tile.
// Dynamic smem: xs[128][129] + ws[128][128]
#define GEMM_SMEM ((128 * 129 + 128 * 128) * 4)
__global__ void k_gemm(const float* __restrict__ x, const float* __restrict__ W, int n) {
    extern __shared__ float smem[];
    float* xs = smem;              // [128][129]
    float* ws = smem + 128 * 129;  // [128][128]

    int tid = threadIdx.x;
    int m0 = blockIdx.x * 128;

    // load W (128x128) cooperatively, float4
    const float4* W4 = (const float4*)W;
    float4* ws4 = (float4*)ws;
    #pragma unroll
    for (int i = tid; i < 128 * 32; i += 256) ws4[i] = W4[i];

    // load x tile (128 rows x 128 cols), padded stride 129 (scalar stores)
    for (int i = tid; i < 128 * 32; i += 256) {
        int r = i >> 5;
        int c4 = (i & 31) * 4;
        float4 v = make_float4(0.f, 0.f, 0.f, 0.f);
        if (m0 + r < n) v = *(const float4*)&x[(size_t)(m0 + r) * CH + c4];
        float* row = xs + r * 129 + c4;
        row[0] = v.x; row[1] = v.y; row[2] = v.z; row[3] = v.w;
    }
    __syncthreads();

    int ty = tid >> 4;   // 0..15
    int tx = tid & 15;   // 0..15
    float acc[8][8];
    #pragma unroll
    for (int i = 0; i < 8; i++)
        #pragma unroll
        for (int j = 0; j < 8; j++) acc[i][j] = 0.f;

    #pragma unroll 4
    for (int k = 0; k < 128; k++) {
        float a[8], b[8];
        #pragma unroll
        for (int i = 0; i < 8; i++) a[i] = xs[(ty + 16 * i) * 129 + k];
        #pragma unroll
        for (int j = 0; j < 8; j++) b[j] = ws[k * 128 + tx + 16 * j];
        #pragma unroll
        for (int i = 0; i < 8; i++)
            #pragma unroll
            for (int j = 0; j < 8; j++) acc[i][j] = fmaf(a[i], b[j], acc[i][j]);
    }

    #pragma unroll
    for (int i = 0; i < 8; i++) {
        int r = m0 + ty + 16 * i;
        if (r < n) {
            float* hp = &g_h[(size_t)r * CH];
            #pragma unroll
            for (int j = 0; j < 8; j++) hp[tx + 16 * j] = acc[i][j];
        }
    }
}

// -------- kernel 5: out[i] = h[i] * dinv[i]^2 (self-loop msg; also init) --------
__global__ void k_selfinit(float* __restrict__ out, int n) {
    int i = blockIdx.x * blockDim.x + threadIdx.x;  // over n*32 float4s
    if (i >= n * 32) return;
    int node = i >> 5;
    float di = g_dinv[node];
    float s = di * di;
    float4 v = ((const float4*)g_h)[i];
    v.x *= s; v.y *= s; v.z *= s; v.w *= s;
    ((float4*)out)[i] = v;
}

// -------- kernel 6: edge scatter. One warp per edge, red.v4.f32 --------
__global__ void k_scatter(const int* __restrict__ src, const int* __restrict__ dst,
                          float* __restrict__ out, int E) {
    int gt = blockIdx.x * blockDim.x + threadIdx.x;
    int e = gt >> 5;
    int lane = gt & 31;
    if (e >= E) return;
    int s = __ldg(&src[e]);
    int d = __ldg(&dst[e]);
    float norm = g_dinv[s] * g_dinv[d];
    float4 v = __ldg(((const float4*)&g_h[(size_t)s * CH]) + lane);
    v.x *= norm; v.y *= norm; v.z *= norm; v.w *= norm;
    float* p = out + (size_t)d * CH + lane * 4;
    asm volatile("red.global.add.v4.f32 [%0], {%1, %2, %3, %4};"
                 :: "l"(p), "f"(v.x), "f"(v.y), "f"(v.z), "f"(v.w)
                 : "memory");
}

// -------- kernel 7: out = relu(out + b) --------
__global__ void k_bias_relu(float* __restrict__ out, const float* __restrict__ b, int n) {
    int i = blockIdx.x * blockDim.x + threadIdx.x;  // over n*32 float4s
    if (i >= n * 32) return;
    float4 v = ((float4*)out)[i];
    float4 bb = ((const float4*)b)[i & 31];
    v.x = fmaxf(v.x + bb.x, 0.f);
    v.y = fmaxf(v.y + bb.y, 0.f);
    v.z = fmaxf(v.z + bb.z, 0.f);
    v.w = fmaxf(v.w + bb.w, 0.f);
    ((float4*)out)[i] = v;
}

extern "C" void kernel_launch(void* const* d_in, const int* in_sizes, int n_in,
                              void* d_out, int out_size) {
    const float* x  = (const float*)d_in[0];
    const int*   ei = (const int*)d_in[1];
    const float* W  = (const float*)d_in[2];
    const float* b  = (const float*)d_in[3];
    float* out = (float*)d_out;

    int n = in_sizes[0] / CH;
    if (n > N_NODES_MAX) n = N_NODES_MAX;
    int E = in_sizes[1] / 2;
    const int* src = ei;
    const int* dst = ei + E;

    // 1) deg = 1
    k_init_deg<<<(n + 255) / 256, 256>>>(n);
    // 2) histogram dst
    k_count<<<(E + 255) / 256, 256>>>(dst, E);
    // 3) dinv
    k_dinv<<<(n + 255) / 256, 256>>>(n);
    // 4) GEMM
    static bool attr_set = false;
    if (!attr_set) {
        cudaFuncSetAttribute(k_gemm, cudaFuncAttributeMaxDynamicSharedMemorySize, GEMM_SMEM);
        attr_set = true;
    }
    k_gemm<<<(n + 127) / 128, 256, GEMM_SMEM>>>(x, W, n);
    // 5) self-loop init of out
    k_selfinit<<<(n * 32 + 255) / 256, 256>>>(out, n);
    // 6) edge scatter (one warp per edge)
    {
        long long threads = (long long)E * 32;
        int blocks = (int)((threads + 255) / 256);
        k_scatter<<<blocks, 256>>>(src, dst, out, E);
    }
    // 7) bias + relu
    k_bias_relu<<<(n * 32 + 255) / 256, 256>>>(out, b, n);
}